// round 8
// baseline (speedup 1.0000x reference)
#include <cuda_runtime.h>
#include <cuda_bf16.h>

#define NB    8
#define NC    512
#define NPIX  4096      // 64*64
#define NCLS  19
#define TGT   512
#define NROW  (NB*NC*2)     // 8192 channel-rows (S then T)

#define FB_PX 128           // pixels per fused block
#define FB_G  4             // channel groups
#define FB_CG (NC/FB_G)     // 128 channels per group
#define FB_T  512           // threads
#define NBLK  (NB*NPIX/FB_PX)  // 256 fused blocks

// dynamic smem layout (floats)
#define SM_SUMS  (NC*NCLS)          // 9728 per tensor
#define OFF_ST   0
#define OFF_TT   SM_SUMS
#define OFF_NSQP (2*SM_SUMS)        // 608 partials (2*19*16)
#define OFF_NSQ  (OFF_NSQP + 608)   // 38
#define OFF_RED  (OFF_NSQ + 40)     // 16*128 = 2048
#define SM_TOT   (OFF_RED + FB_G*4*FB_PX)
#define SM_BYTES (SM_TOT*4)

// ---------------- device scratch (static, no allocations) ----------------
__device__ unsigned char g_lab[NB*NPIX];
__device__ float g_cnt [NB*NCLS];
__device__ float g_sumS[NB*NC*NCLS];
__device__ float g_sumT[NB*NC*NCLS];
__device__ float g_blockred[NBLK];

// ---------------- K0: nearest-resize labels + per-batch class histogram ----
__global__ void k_prep(const int* __restrict__ tgt) {
    int b = blockIdx.x;
    __shared__ int hist[NCLS];
    if (threadIdx.x < NCLS) hist[threadIdx.x] = 0;
    __syncthreads();
    for (int n = threadIdx.x; n < NPIX; n += blockDim.x) {
        int h = n >> 6, w = n & 63;
        int k = tgt[b*TGT*TGT + (h*8)*TGT + (w*8)];   // nearest: idx*8
        unsigned char lab = (k >= 0 && k < NCLS) ? (unsigned char)k : (unsigned char)255;
        g_lab[b*NPIX + n] = lab;
        if (lab != 255) atomicAdd(&hist[k], 1);
    }
    __syncthreads();
    if (threadIdx.x < NCLS) g_cnt[b*NCLS + threadIdx.x] = (float)hist[threadIdx.x];
}

// ---------------- K1: warp-per-channel class sums, lane-private bins ------
__global__ __launch_bounds__(256) void k_classsum(const float* __restrict__ S,
                                                  const float* __restrict__ T) {
    __shared__ float bins[8][NCLS+1][32];   // slot NCLS = trash for invalid labels
    int t    = threadIdx.x;
    int w    = t >> 5;
    int lane = t & 31;

    int r = blockIdx.x * 8 + w;          // 0..NROW-1
    int tensor = r >> 12;                // 0 = S, 1 = T
    int bc = r & (NB*NC - 1);
    int b  = bc >> 9;
    const float* F = tensor ? T : S;
    float* outp    = tensor ? g_sumT : g_sumS;

    #pragma unroll
    for (int k = 0; k <= NCLS; k++) bins[w][k][lane] = 0.f;

    const float4* row = (const float4*)(F + (size_t)bc * NPIX);
    const uchar4* lb  = (const uchar4*)&g_lab[b*NPIX];
    float* mb = &bins[w][0][lane];

    #pragma unroll 4
    for (int i = lane; i < NPIX/4; i += 32) {
        float4 v = row[i];
        uchar4 l = lb[i];
        int kx = l.x < NCLS ? l.x : NCLS;
        int ky = l.y < NCLS ? l.y : NCLS;
        int kz = l.z < NCLS ? l.z : NCLS;
        int kw = l.w < NCLS ? l.w : NCLS;
        mb[32*kx] += v.x;
        mb[32*ky] += v.y;
        mb[32*kz] += v.z;
        mb[32*kw] += v.w;
    }
    __syncwarp();

    size_t ob = (size_t)bc * NCLS;
    #pragma unroll
    for (int k = 0; k < NCLS; k++) {
        float v = bins[w][k][lane];
        #pragma unroll
        for (int o = 16; o > 0; o >>= 1) v += __shfl_down_sync(0xFFFFFFFFu, v, o);
        if (lane == 0) outp[ob + k] = v;
    }
}

// ---------------- K2 (fused): dot/norm accumulation + nsq + cosine + MSE ---
__global__ __launch_bounds__(FB_T) void k_fused(const float* __restrict__ S,
                                                const float* __restrict__ T) {
    extern __shared__ float sm[];
    float* shS  = sm + OFF_ST;
    float* shT  = sm + OFF_TT;
    float* nsqp = sm + OFF_NSQP;
    float* nsq  = sm + OFF_NSQ;
    float* red  = sm + OFF_RED;

    int blk = blockIdx.x;             // 0..255
    int gpx = blk * FB_PX;            // global pixel base
    int b   = gpx >> 12;              // 32 blocks per batch
    int px0 = gpx & (NPIX-1);
    int t   = threadIdx.x;
    int p   = t & (FB_PX-1);          // pixel within block
    int g   = t >> 7;                 // channel group 0..3

    // stage full per-batch class-sum tables
    size_t sb = (size_t)b * NC * NCLS;
    for (int i = t; i < SM_SUMS; i += FB_T) {
        shS[i] = g_sumS[sb + i];
        shT[i] = g_sumT[sb + i];
    }

    unsigned char lab = g_lab[b*NPIX + px0 + p];
    int k = (lab < NCLS) ? lab : 0;
    __syncthreads();

    // main accumulation: 128 channels per thread
    const float* pS = S + ((size_t)(b*NC + g*FB_CG))*NPIX + px0 + p;
    const float* pT = T + ((size_t)(b*NC + g*FB_CG))*NPIX + px0 + p;
    const float* mS = shS + (g*FB_CG)*NCLS + k;
    const float* mT = shT + (g*FB_CG)*NCLS + k;

    float dS = 0.f, fS = 0.f, dT = 0.f, fT = 0.f;
    #pragma unroll 8
    for (int c = 0; c < FB_CG; c++) {
        float vS = pS[(size_t)c*NPIX];
        float vT = pT[(size_t)c*NPIX];
        float sA = mS[c*NCLS];
        float tA = mT[c*NCLS];
        fS += vS*vS;  dS += vS*sA;
        fT += vT*vT;  dT += vT*tA;
    }
    red[(g*4+0)*FB_PX + p] = dS;
    red[(g*4+1)*FB_PX + p] = fS;
    red[(g*4+2)*FB_PX + p] = dT;
    red[(g*4+3)*FB_PX + p] = fT;

    // nsq partials: 2 tensors * 19 classes * 16 slices of 32 channels
    if (t < 2*NCLS*16 - 0) { /* 608 threads needed; only 512 exist -> two rounds */ }
    if (t < NCLS*16) {                 // S partials: 304 threads
        int kk = t >> 4, j = t & 15;
        float a = 0.f;
        #pragma unroll 8
        for (int c = j*32; c < j*32+32; c++) a += shS[c*NCLS + kk]*shS[c*NCLS + kk];
        nsqp[t] = a;
    } else if (t < 2*NCLS*16) {        // T partials: next 304 threads (608 <= 512? no!)
        int tt = t - NCLS*16;
        int kk = tt >> 4, j = tt & 15;
        float a = 0.f;
        #pragma unroll 8
        for (int c = j*32; c < j*32+32; c++) a += shT[c*NCLS + kk]*shT[c*NCLS + kk];
        nsqp[t] = a;
    }
    // threads 512..607 don't exist: cover remainder (t in [0,96) handles tail)
    if (t < 2*NCLS*16 - FB_T) {        // 96 remaining T-partials
        int tt = t + (FB_T - NCLS*16); // offset into T range
        int kk = tt >> 4, j = tt & 15;
        float a = 0.f;
        #pragma unroll 8
        for (int c = j*32; c < j*32+32; c++) a += shT[c*NCLS + kk]*shT[c*NCLS + kk];
        nsqp[NCLS*16 + tt] = a;
    }
    __syncthreads();
    if (t < 2*NCLS) {                  // 38 threads finalize nsq
        int base = t*16;
        float a = 0.f;
        #pragma unroll
        for (int j = 0; j < 16; j++) a += nsqp[base + j];
        nsq[t] = a;
    }
    __syncthreads();

    float blockpart = 0.f;
    if (t < FB_PX) {
        float DS = red[(0*4+0)*FB_PX+t] + red[(1*4+0)*FB_PX+t] + red[(2*4+0)*FB_PX+t] + red[(3*4+0)*FB_PX+t];
        float FS = red[(0*4+1)*FB_PX+t] + red[(1*4+1)*FB_PX+t] + red[(2*4+1)*FB_PX+t] + red[(3*4+1)*FB_PX+t];
        float DT = red[(0*4+2)*FB_PX+t] + red[(1*4+2)*FB_PX+t] + red[(2*4+2)*FB_PX+t] + red[(3*4+2)*FB_PX+t];
        float FT = red[(0*4+3)*FB_PX+t] + red[(1*4+3)*FB_PX+t] + red[(2*4+3)*FB_PX+t] + red[(3*4+3)*FB_PX+t];
        unsigned char lb2 = g_lab[b*NPIX + px0 + t];
        float pS_, pT_;
        if (lb2 < NCLS) {
            float cnt = g_cnt[b*NCLS + lb2];
            float inv = 1.f/(cnt + 1e-6f);
            float nfS = sqrtf(FS);
            float nmS = sqrtf(nsq[lb2]) * inv;
            pS_ = (DS*inv) / (fmaxf(nfS, 1e-8f) * fmaxf(nmS, 1e-8f));
            float nfT = sqrtf(FT);
            float nmT = sqrtf(nsq[NCLS + lb2]) * inv;
            pT_ = (DT*inv) / (fmaxf(nfT, 1e-8f) * fmaxf(nmT, 1e-8f));
        } else {
            float nfS = fmaxf(sqrtf(FS), 1e-8f); pS_ = FS/(nfS*nfS);
            float nfT = fmaxf(sqrtf(FT), 1e-8f); pT_ = FT/(nfT*nfT);
        }
        float d = pS_ - pT_;
        blockpart = d*d;
    }
    // reduce 128 values (4 warps active)
    #pragma unroll
    for (int o = 16; o > 0; o >>= 1) blockpart += __shfl_down_sync(0xFFFFFFFFu, blockpart, o);
    __shared__ float sw[4];
    if (t < FB_PX && (t & 31) == 0) sw[t >> 5] = blockpart;
    __syncthreads();
    if (t == 0) g_blockred[blk] = (sw[0] + sw[1]) + (sw[2] + sw[3]);
}

// ---------------- K3: final deterministic reduction to scalar -------------
__global__ void k_out(float* __restrict__ out) {
    int t = threadIdx.x;   // 256 threads
    float v = g_blockred[t];
    #pragma unroll
    for (int o = 16; o > 0; o >>= 1) v += __shfl_down_sync(0xFFFFFFFFu, v, o);
    __shared__ float s[8];
    if ((t & 31) == 0) s[t >> 5] = v;
    __syncthreads();
    if (t == 0) {
        float a = ((s[0]+s[1])+(s[2]+s[3])) + ((s[4]+s[5])+(s[6]+s[7]));
        out[0] = a * (1.f/32768.f);
    }
}

extern "C" void kernel_launch(void* const* d_in, const int* in_sizes, int n_in,
                              void* d_out, int out_size) {
    const float* S   = (const float*)d_in[0];
    const float* T   = (const float*)d_in[1];
    const int*   tgt = (const int*)d_in[2];
    float* out = (float*)d_out;

    cudaFuncSetAttribute(k_fused, cudaFuncAttributeMaxDynamicSharedMemorySize, SM_BYTES);

    k_prep    <<<NB, 256>>>(tgt);
    k_classsum<<<NROW/8, 256>>>(S, T);
    k_fused   <<<NBLK, FB_T, SM_BYTES>>>(S, T);
    k_out     <<<1, NBLK>>>(out);
}

// round 9
// speedup vs baseline: 1.2517x; 1.2517x over previous
#include <cuda_runtime.h>
#include <cuda_bf16.h>

#define NB    8
#define NC    512
#define NPIX  4096      // 64*64
#define NCLS  19
#define TGT   512
#define NSPLIT 16
#define CSPAN (NC/NSPLIT)   // 32
#define K3_T  256
#define PXB   (K3_T*2)      // 512 pixels per K3 block
#define NTILE (NPIX/PXB)    // 8
#define NROW  (NB*NC*2)     // 8192 channel-rows (S then T)
#define NFBLK 128           // k_final blocks

// ---------------- device scratch (static, no allocations) ----------------
__device__ unsigned char g_lab[NB*NPIX];
__device__ float g_cnt [NB*NCLS];
__device__ float g_sumS[NB*NC*NCLS];
__device__ float g_sumT[NB*NC*NCLS];
__device__ float g_nsqS[NB*NCLS];
__device__ float g_nsqT[NB*NCLS];
__device__ float g_part[NSPLIT][4][NB*NPIX];   // dotS,fsqS,dotT,fsqT partials
__device__ float g_blockred[NFBLK];
__device__ unsigned int g_ticket;              // zero-initialized; self-resets

// ---------------- K0: nearest-resize labels + per-batch class histogram ----
__global__ void k_prep(const int* __restrict__ tgt) {
    int b = blockIdx.x;
    __shared__ int hist[NCLS];
    if (threadIdx.x < NCLS) hist[threadIdx.x] = 0;
    __syncthreads();
    for (int n = threadIdx.x; n < NPIX; n += blockDim.x) {
        int h = n >> 6, w = n & 63;
        int k = tgt[b*TGT*TGT + (h*8)*TGT + (w*8)];   // nearest: idx*8
        unsigned char lab = (k >= 0 && k < NCLS) ? (unsigned char)k : (unsigned char)255;
        g_lab[b*NPIX + n] = lab;
        if (lab != 255) atomicAdd(&hist[k], 1);
    }
    __syncthreads();
    if (threadIdx.x < NCLS) g_cnt[b*NCLS + threadIdx.x] = (float)hist[threadIdx.x];
}

// ---------------- K1: warp-per-channel class sums, lane-private bins ------
// bins[w][k][lane]: bank = lane -> conflict-free, no atomics, no barriers.
__global__ __launch_bounds__(256) void k_classsum(const float* __restrict__ S,
                                                  const float* __restrict__ T) {
    __shared__ float bins[8][NCLS+1][32];   // slot NCLS = trash for invalid labels
    int t    = threadIdx.x;
    int w    = t >> 5;
    int lane = t & 31;

    int r = blockIdx.x * 8 + w;          // 0..NROW-1
    int tensor = r >> 12;                // 0 = S, 1 = T
    int bc = r & (NB*NC - 1);
    int b  = bc >> 9;
    const float* F = tensor ? T : S;
    float* outp    = tensor ? g_sumT : g_sumS;

    #pragma unroll
    for (int k = 0; k <= NCLS; k++) bins[w][k][lane] = 0.f;

    const float4* row = (const float4*)(F + (size_t)bc * NPIX);
    const uchar4* lb  = (const uchar4*)&g_lab[b*NPIX];
    float* mb = &bins[w][0][lane];

    #pragma unroll 4
    for (int i = lane; i < NPIX/4; i += 32) {
        float4 v = row[i];
        uchar4 l = lb[i];
        int kx = l.x < NCLS ? l.x : NCLS;
        int ky = l.y < NCLS ? l.y : NCLS;
        int kz = l.z < NCLS ? l.z : NCLS;
        int kw = l.w < NCLS ? l.w : NCLS;
        mb[32*kx] += v.x;
        mb[32*ky] += v.y;
        mb[32*kz] += v.z;
        mb[32*kw] += v.w;
    }
    __syncwarp();

    size_t ob = (size_t)bc * NCLS;
    #pragma unroll
    for (int k = 0; k < NCLS; k++) {
        float v = bins[w][k][lane];
        #pragma unroll
        for (int o = 16; o > 0; o >>= 1) v += __shfl_down_sync(0xFFFFFFFFu, v, o);
        if (lane == 0) outp[ob + k] = v;
    }
}

// ---------------- K2: per-(b,k) squared norm of class sums ----------------
__global__ void k_stats() {
    int b = blockIdx.x, k = blockIdx.y, t = threadIdx.x;
    float aS = 0.f, aT = 0.f;
    for (int c = t; c < NC; c += 256) {
        float s = g_sumS[((size_t)b*NC + c)*NCLS + k]; aS += s*s;
        float u = g_sumT[((size_t)b*NC + c)*NCLS + k]; aT += u*u;
    }
    #pragma unroll
    for (int o = 16; o > 0; o >>= 1) {
        aS += __shfl_down_sync(0xFFFFFFFFu, aS, o);
        aT += __shfl_down_sync(0xFFFFFFFFu, aT, o);
    }
    __shared__ float sS[8], sT[8];
    if ((t & 31) == 0) { sS[t >> 5] = aS; sT[t >> 5] = aT; }
    __syncthreads();
    if (t == 0) {
        float s = 0.f, u = 0.f;
        #pragma unroll
        for (int w = 0; w < 8; w++) { s += sS[w]; u += sT[w]; }
        g_nsqS[b*NCLS + k] = s;
        g_nsqT[b*NCLS + k] = u;
    }
}

// ---------------- K3: main pass — per-pixel ||f||^2 and f·sums[class] -----
__global__ __launch_bounds__(K3_T) void k_main(const float* __restrict__ S,
                                               const float* __restrict__ T) {
    int tile = blockIdx.x;   // 0..NTILE-1
    int b    = blockIdx.y;   // 0..7
    int sp   = blockIdx.z;   // 0..NSPLIT-1
    __shared__ float shS[CSPAN*NCLS];   // 32*19 = 608 floats
    __shared__ float shT[CSPAN*NCLS];
    int t = threadIdx.x;
    int c0 = sp*CSPAN;

    for (int i = t; i < CSPAN*NCLS; i += K3_T) {
        shS[i] = g_sumS[((size_t)(b*NC + c0))*NCLS + i];
        shT[i] = g_sumT[((size_t)(b*NC + c0))*NCLS + i];
    }
    int px = tile*PXB + 2*t;
    unsigned char lx = g_lab[b*NPIX + px];
    unsigned char ly = g_lab[b*NPIX + px + 1];
    int k0 = (lx < NCLS) ? lx : 0;   // dot unused for invalid labels
    int k1 = (ly < NCLS) ? ly : 0;
    __syncthreads();

    const float2* pS = (const float2*)(S + ((size_t)(b*NC + c0))*NPIX + px);
    const float2* pT = (const float2*)(T + ((size_t)(b*NC + c0))*NPIX + px);

    float dS0=0,dS1=0, fS0=0,fS1=0;
    float dT0=0,dT1=0, fT0=0,fT1=0;
    #pragma unroll 8
    for (int c = 0; c < CSPAN; c++) {
        float2 vS = pS[c*(NPIX/2)];
        float2 vT = pT[c*(NPIX/2)];
        float sA = shS[c*NCLS + k0], sB = shS[c*NCLS + k1];
        float tA = shT[c*NCLS + k0], tB = shT[c*NCLS + k1];
        fS0 += vS.x*vS.x;  dS0 += vS.x*sA;
        fS1 += vS.y*vS.y;  dS1 += vS.y*sB;
        fT0 += vT.x*vT.x;  dT0 += vT.x*tA;
        fT1 += vT.y*vT.y;  dT1 += vT.y*tB;
    }
    int gi = b*NPIX + px;
    *(float2*)&g_part[sp][0][gi] = make_float2(dS0, dS1);
    *(float2*)&g_part[sp][1][gi] = make_float2(fS0, fS1);
    *(float2*)&g_part[sp][2][gi] = make_float2(dT0, dT1);
    *(float2*)&g_part[sp][3][gi] = make_float2(fT0, fT1);
}

// ---- K4: combine splits, cosine sims, MSE partial; last block finalizes ---
__global__ void k_final(float* __restrict__ out) {
    int t = threadIdx.x;
    int gi = blockIdx.x*256 + t;   // 128 blocks * 256 = 32768 pixels
    float dS=0,fS=0,dT=0,fT=0;
    #pragma unroll
    for (int s = 0; s < NSPLIT; s++) {
        dS += g_part[s][0][gi];
        fS += g_part[s][1][gi];
        dT += g_part[s][2][gi];
        fT += g_part[s][3][gi];
    }
    int b = gi >> 12;
    int k = g_lab[gi];
    float pS_, pT_;
    if (k < NCLS) {
        float cnt = g_cnt[b*NCLS + k];
        float inv = 1.f/(cnt + 1e-6f);
        float nfS = sqrtf(fS);
        float nmS = sqrtf(g_nsqS[b*NCLS + k]) * inv;
        pS_ = (dS*inv) / (fmaxf(nfS, 1e-8f) * fmaxf(nmS, 1e-8f));
        float nfT = sqrtf(fT);
        float nmT = sqrtf(g_nsqT[b*NCLS + k]) * inv;
        pT_ = (dT*inv) / (fmaxf(nfT, 1e-8f) * fmaxf(nmT, 1e-8f));
    } else {
        // invalid label: center = f  ->  cos(f, f)
        float nfS = fmaxf(sqrtf(fS), 1e-8f); pS_ = fS/(nfS*nfS);
        float nfT = fmaxf(sqrtf(fT), 1e-8f); pT_ = fT/(nfT*nfT);
    }
    float d = pS_ - pT_;
    float v = d*d;
    #pragma unroll
    for (int o = 16; o > 0; o >>= 1) v += __shfl_down_sync(0xFFFFFFFFu, v, o);
    __shared__ float sw[8];
    if ((t & 31) == 0) sw[t >> 5] = v;
    __syncthreads();
    __shared__ bool last;
    if (t == 0) {
        float a = 0.f;
        #pragma unroll
        for (int w = 0; w < 8; w++) a += sw[w];
        g_blockred[blockIdx.x] = a;
        __threadfence();
        unsigned int tk = atomicAdd(&g_ticket, 1u);
        last = (tk == NFBLK - 1);
    }
    __syncthreads();
    if (last) {
        __threadfence();                 // acquire: see all g_blockred writes
        if (t < NFBLK) {
            float v2 = g_blockred[t];
            #pragma unroll
            for (int o = 16; o > 0; o >>= 1) v2 += __shfl_down_sync(0xFFFFFFFFu, v2, o);
            __shared__ float s2[4];
            if ((t & 31) == 0) s2[t >> 5] = v2;
            __syncwarp();
            if (t == 0) {
                // warps 0..3 of the first 128 threads wrote s2; wait via barrier below
            }
        }
        __syncthreads();
        if (t == 0) {
            // re-read partial warp sums deterministically
            extern __shared__ float dummy[]; // none; do serial fixed-order sum instead
            float a = 0.f;
            for (int i = 0; i < NFBLK; i++) a += g_blockred[i];
            out[0] = a * (1.f/32768.f);
            g_ticket = 0;                // reset for next graph replay
        }
    }
}

extern "C" void kernel_launch(void* const* d_in, const int* in_sizes, int n_in,
                              void* d_out, int out_size) {
    const float* S   = (const float*)d_in[0];
    const float* T   = (const float*)d_in[1];
    const int*   tgt = (const int*)d_in[2];
    float* out = (float*)d_out;

    k_prep    <<<NB, 256>>>(tgt);
    k_classsum<<<NROW/8, 256>>>(S, T);
    k_stats   <<<dim3(NB, NCLS), 256>>>();
    k_main    <<<dim3(NTILE, NB, NSPLIT), K3_T>>>(S, T);
    k_final   <<<NFBLK, 256>>>(out);
}